// round 16
// baseline (speedup 1.0000x reference)
#include <cuda_runtime.h>
#include <cuda_bf16.h>
#include <cuda_fp16.h>
#include <math.h>

#define NN 50000
#define EE 800000
#define NIN 256
#define NH 128
#define NOUT 64
#define NHOP 10
#define NTILE 391          // ceil(NN/128)

typedef unsigned int u32;

// ---------------- scratch (static device memory; no allocations) -------------
__device__ float g_x [(size_t)NN * NH];   // fc1 output = h_0
__device__ float g_h [(size_t)NN * NH];   // current h_i (i>=1)
__device__ float g_u [(size_t)NN * NH];   // agg output (pre-GEMM)
__device__ __align__(16) __half g_xf16[(size_t)NN * NH];  // fp16 copy of x (gather plane)
__device__ __align__(16) __half g_hf16[(size_t)NN * NH];  // fp16 copy of h (gather plane)
__device__ float g_x1all[NHOP * NN];
__device__ float g_w2all[NHOP * NN];
__device__ float g_h1[NN];
__device__ float g_h1x[NN];               // sink for last hop's unused h1
__device__ float g_av1[NHOP * NH];        // a1_i @ W_i
__device__ float g_av2[NHOP * NH];        // a2_i @ W_i
__device__ float g_cc[NHOP * 2];          // c1_i = a1_i.b_i, c2_i = a2_i.b_i
__device__ int   g_deg[NN];
__device__ int   g_rowptr[NN + 1];
__device__ int   g_cursor[NN];
__device__ int   g_et[EE];
// pre-split weights (bf16 hi/lo planes)
__device__ __nv_bfloat16 g_w1h[128 * 256], g_w1l[128 * 256];
__device__ __nv_bfloat16 g_wsh[NHOP * 128 * 128], g_wsl[NHOP * 128 * 128];
__device__ __nv_bfloat16 g_w2h[64 * 128],  g_w2l[64 * 128];

// ---------------- mma / ldmatrix helpers --------------------------------------
__device__ __forceinline__ void mma_bf16(float* d, const u32* a, const u32* b) {
    asm volatile(
        "mma.sync.aligned.m16n8k16.row.col.f32.bf16.bf16.f32 "
        "{%0,%1,%2,%3}, {%4,%5,%6,%7}, {%8,%9}, {%0,%1,%2,%3};"
        : "+f"(d[0]), "+f"(d[1]), "+f"(d[2]), "+f"(d[3])
        : "r"(a[0]), "r"(a[1]), "r"(a[2]), "r"(a[3]), "r"(b[0]), "r"(b[1]));
}

__device__ __forceinline__ void ldsm_x4(u32& r0, u32& r1, u32& r2, u32& r3, u32 addr) {
    asm volatile("ldmatrix.sync.aligned.m8n8.x4.shared.b16 {%0,%1,%2,%3}, [%4];"
        : "=r"(r0), "=r"(r1), "=r"(r2), "=r"(r3) : "r"(addr));
}

// ---------------- weight pre-split kernel ------------------------------------
__global__ void convW_kernel(const float* __restrict__ fc1W,
                             const float* __restrict__ fcsW,
                             const float* __restrict__ fc2W) {
    int i = blockIdx.x * blockDim.x + threadIdx.x;
    float v;
    __nv_bfloat16 *H, *L;
    if (i < 32768) {
        v = fc1W[i]; H = g_w1h + i; L = g_w1l + i;
    } else if (i < 32768 + NHOP * 16384) {
        int j = i - 32768;
        v = fcsW[j]; H = g_wsh + j; L = g_wsl + j;
    } else if (i < 32768 + NHOP * 16384 + 8192) {
        int j = i - 32768 - NHOP * 16384;
        v = fc2W[j]; H = g_w2h + j; L = g_w2l + j;
    } else return;
    __nv_bfloat16 h = __float2bfloat16(v);
    *H = h;
    *L = __float2bfloat16(v - __bfloat162float(h));
}

// ---------------- attention-vector precompute --------------------------------
__global__ void prepvec_kernel(const float* __restrict__ fcsW, const float* __restrict__ fcsb,
                               const float* __restrict__ a1, const float* __restrict__ a2) {
    int hop = blockIdx.x;
    int tid = threadIdx.x;
    __shared__ float a1s[128], a2s[128];
    a1s[tid] = a1[hop * 128 + tid];
    a2s[tid] = a2[hop * 128 + tid];
    __syncthreads();
    const float* W = fcsW + (size_t)hop * 16384;
    float s1 = 0.f, s2 = 0.f;
    for (int j = 0; j < 128; j++) {
        float w = W[j * 128 + tid];
        s1 = fmaf(a1s[j], w, s1);
        s2 = fmaf(a2s[j], w, s2);
    }
    g_av1[hop * 128 + tid] = s1;
    g_av2[hop * 128 + tid] = s2;
    if (tid == 0) {
        float c1 = 0.f, c2 = 0.f;
        const float* b = fcsb + hop * 128;
        for (int j = 0; j < 128; j++) { c1 = fmaf(a1s[j], b[j], c1); c2 = fmaf(a2s[j], b[j], c2); }
        g_cc[hop * 2] = c1;
        g_cc[hop * 2 + 1] = c2;
    }
}

// ---------------- per-node scalars for all hops (reads x once) ----------------
__global__ void xdots_kernel(const float* __restrict__ xg) {
    int n = (blockIdx.x * blockDim.x + threadIdx.x) >> 5;
    int lane = threadIdx.x & 31;
    if (n >= NN) return;
    float4 xv = *(const float4*)(xg + (size_t)n * NH + lane * 4);
#pragma unroll
    for (int i = 0; i < NHOP; i++) {
        float4 v1 = __ldg((const float4*)(g_av1 + i * 128 + lane * 4));
        float4 v2 = __ldg((const float4*)(g_av2 + i * 128 + lane * 4));
        float p1 = xv.x * v1.x + xv.y * v1.y + xv.z * v1.z + xv.w * v1.w;
        float p2 = xv.x * v2.x + xv.y * v2.y + xv.z * v2.z + xv.w * v2.w;
#pragma unroll
        for (int off = 16; off; off >>= 1) {
            p1 += __shfl_xor_sync(0xffffffffu, p1, off);
            p2 += __shfl_xor_sync(0xffffffffu, p2, off);
        }
        if (lane == 0) {
            float c1 = g_cc[i * 2], c2 = g_cc[i * 2 + 1];
            float x1 = p1 + c1;
            g_x1all[i * NN + n] = x1;
            float z = x1 + p2 + c2;
            z = z > 0.f ? z : 0.2f * z;
            g_w2all[i * NN + n] = __expf(z);
            if (i == 0) g_h1[n] = p2 + c2;
        }
    }
}

// ---------------- CSR build --------------------------------------------------
__global__ void hist_kernel(const int* __restrict__ s) {
    int e = blockIdx.x * blockDim.x + threadIdx.x;
    if (e < EE) atomicAdd(&g_deg[s[e]], 1);
}

#define SCAN_SMEM (NN * 4)
__global__ void scan_kernel() {
    extern __shared__ int sdeg[];
    __shared__ int wsum[32];
    __shared__ int totalS;
    const int tid = threadIdx.x, lane = tid & 31, wid = tid >> 5;
    for (int i = tid; i < NN; i += 1024) sdeg[i] = g_deg[i];
    __syncthreads();
    const int CH = (NN + 1023) / 1024;   // 49
    const int base = tid * CH;
    int s = 0;
#pragma unroll 7
    for (int i = 0; i < CH; i++) {
        int idx = base + i;
        if (idx < NN) s += sdeg[idx];
    }
    int v = s;
#pragma unroll
    for (int off = 1; off < 32; off <<= 1) {
        int n = __shfl_up_sync(0xffffffffu, v, off);
        if (lane >= off) v += n;
    }
    if (lane == 31) wsum[wid] = v;
    __syncthreads();
    if (wid == 0) {
        int w = wsum[lane];
#pragma unroll
        for (int off = 1; off < 32; off <<= 1) {
            int n = __shfl_up_sync(0xffffffffu, w, off);
            if (lane >= off) w += n;
        }
        wsum[lane] = w;
        if (lane == 31) totalS = w;
    }
    __syncthreads();
    int excl = v - s + (wid ? wsum[wid - 1] : 0);
    int run = excl;
#pragma unroll 7
    for (int i = 0; i < CH; i++) {
        int idx = base + i;
        if (idx < NN) {
            int d = sdeg[idx];
            sdeg[idx] = run;
            run += d;
        }
    }
    __syncthreads();
    for (int i = tid; i < NN; i += 1024) {
        int p = sdeg[i];
        g_cursor[i] = p;
        g_rowptr[i] = p;
    }
    if (tid == 0) g_rowptr[NN] = totalS;
}

__global__ void scatter_kernel(const int* __restrict__ s, const int* __restrict__ t) {
    int e = blockIdx.x * blockDim.x + threadIdx.x;
    if (e < EE) {
        int pos = atomicAdd(&g_cursor[s[e]], 1);
        g_et[pos] = t[e];
    }
}

// ---------------- bf16 3-product mma GEMM (ldmatrix fragment loads) -----------
// C[nrows,BN] = epi(A[nrows,KTOT] @ W[BN,KTOT]^T + bias), W pre-split hi/lo.
// MODE 0: epi = (ACT? relu : id). MODE 3: epi = elu, plus h1o[row] = C.a2g + *c2p.
// H16: also write fp16 copy of C (gather plane for the next agg).
template <int KTOT, int BN, int ACT, int MODE, int H16>
__global__ __launch_bounds__(256)
void mma_gemm(const float* __restrict__ Ag,
              const __nv_bfloat16* __restrict__ Whg, const __nv_bfloat16* __restrict__ Wlg,
              const float* __restrict__ biasg,
              float* __restrict__ Cg, __half* __restrict__ hf16o,
              const float* __restrict__ a2g, float* __restrict__ h1o,
              const float* __restrict__ c2p,
              int nrows) {
    constexpr int NT  = BN / 32;
    constexpr int NCH = KTOT / 32;
    constexpr int WIT = BN / 64;
    constexpr int SP  = 20;

    __shared__ float biasS[BN];
    __shared__ float a2S[128];
    __shared__ float s2p[4][128];
    __shared__ __align__(16) u32 Ah[128 * SP], Al[128 * SP];
    __shared__ __align__(16) u32 Wsh[BN * SP], Wsl[BN * SP];

    const int tid = threadIdx.x;
    const int wid = tid >> 5, lane = tid & 31;
    const int wm = wid >> 2, wn = wid & 3;
    const int rbase = blockIdx.x * 128;

    if (tid < BN) biasS[tid] = biasg[tid];
    if (MODE == 3 && tid < 128) a2S[tid] = a2g[tid];

    const u32 AhS = (u32)__cvta_generic_to_shared(Ah);
    const u32 AlS = (u32)__cvta_generic_to_shared(Al);
    const u32 WhS = (u32)__cvta_generic_to_shared(Wsh);
    const u32 WlS = (u32)__cvta_generic_to_shared(Wsl);
    const u32 aoff = (u32)(((wm * 64 + (lane & 15)) * SP + (lane >> 4) * 4) * 4);
    const u32 boff = (u32)(((wn * (NT * 8) + (lane & 7) + ((lane >> 4) << 3)) * SP
                           + ((lane >> 3) & 1) * 4) * 4);

    float acc[4][NT][4];
#pragma unroll
    for (int mt = 0; mt < 4; mt++)
#pragma unroll
        for (int nt = 0; nt < NT; nt++)
#pragma unroll
            for (int q = 0; q < 4; q++) acc[mt][nt][q] = 0.f;

    float4 pa[4];
    uint4 pwh[WIT], pwl[WIT];
#pragma unroll
    for (int it = 0; it < 4; it++) {
        int idx = tid + it * 256;
        int r = idx >> 3, kq = idx & 7;
        int row = rbase + r;
        pa[it] = (row < nrows) ? *(const float4*)(Ag + (size_t)row * KTOT + kq * 4)
                               : make_float4(0.f, 0.f, 0.f, 0.f);
    }
#pragma unroll
    for (int it = 0; it < WIT; it++) {
        int idx = tid + it * 256;
        int r = idx >> 2, q = idx & 3;
        pwh[it] = ((const uint4*)(Whg + (size_t)r * KTOT))[q];
        pwl[it] = ((const uint4*)(Wlg + (size_t)r * KTOT))[q];
    }

    for (int c = 0; c < NCH; c++) {
#pragma unroll
        for (int it = 0; it < 4; it++) {
            int idx = tid + it * 256;
            int r = idx >> 3, kq = idx & 7;
            float4 v = pa[it];
            __nv_bfloat162 hxy = __floats2bfloat162_rn(v.x, v.y);
            __nv_bfloat162 hzw = __floats2bfloat162_rn(v.z, v.w);
            float2 fxy = __bfloat1622float2(hxy);
            float2 fzw = __bfloat1622float2(hzw);
            __nv_bfloat162 lxy = __floats2bfloat162_rn(v.x - fxy.x, v.y - fxy.y);
            __nv_bfloat162 lzw = __floats2bfloat162_rn(v.z - fzw.x, v.w - fzw.y);
            int o = r * SP + kq * 2;
            Ah[o]     = *(u32*)&hxy;  Ah[o + 1] = *(u32*)&hzw;
            Al[o]     = *(u32*)&lxy;  Al[o + 1] = *(u32*)&lzw;
        }
#pragma unroll
        for (int it = 0; it < WIT; it++) {
            int idx = tid + it * 256;
            int r = idx >> 2, q = idx & 3;
            *(uint4*)&Wsh[r * SP + q * 4] = pwh[it];
            *(uint4*)&Wsl[r * SP + q * 4] = pwl[it];
        }
        __syncthreads();

        if (c + 1 < NCH) {
            const int kc = (c + 1) * 32;
#pragma unroll
            for (int it = 0; it < 4; it++) {
                int idx = tid + it * 256;
                int r = idx >> 3, kq = idx & 7;
                int row = rbase + r;
                pa[it] = (row < nrows) ? *(const float4*)(Ag + (size_t)row * KTOT + kc + kq * 4)
                                       : make_float4(0.f, 0.f, 0.f, 0.f);
            }
#pragma unroll
            for (int it = 0; it < WIT; it++) {
                int idx = tid + it * 256;
                int r = idx >> 2, q = idx & 3;
                pwh[it] = ((const uint4*)(Whg + (size_t)r * KTOT + kc))[q];
                pwl[it] = ((const uint4*)(Wlg + (size_t)r * KTOT + kc))[q];
            }
        }

#pragma unroll
        for (int s = 0; s < 2; s++) {
            u32 ah[4][4], al[4][4], bh[NT][2], bl[NT][2];
            const u32 soff = (u32)(s * 8 * 4);
#pragma unroll
            for (int mt = 0; mt < 4; mt++) {
                u32 moff = aoff + (u32)(mt * 16 * SP * 4) + soff;
                ldsm_x4(ah[mt][0], ah[mt][1], ah[mt][2], ah[mt][3], AhS + moff);
                ldsm_x4(al[mt][0], al[mt][1], al[mt][2], al[mt][3], AlS + moff);
            }
#pragma unroll
            for (int np = 0; np < NT / 2; np++) {
                u32 noff = boff + (u32)(np * 16 * SP * 4) + soff;
                ldsm_x4(bh[2 * np][0], bh[2 * np][1], bh[2 * np + 1][0], bh[2 * np + 1][1],
                        WhS + noff);
                ldsm_x4(bl[2 * np][0], bl[2 * np][1], bl[2 * np + 1][0], bl[2 * np + 1][1],
                        WlS + noff);
            }
#pragma unroll
            for (int mt = 0; mt < 4; mt++)
#pragma unroll
                for (int nt = 0; nt < NT; nt++) {
                    mma_bf16(acc[mt][nt], ah[mt], bh[nt]);
                    mma_bf16(acc[mt][nt], ah[mt], bl[nt]);
                    mma_bf16(acc[mt][nt], al[mt], bh[nt]);
                }
        }
        if (c + 1 < NCH) __syncthreads();
    }

#pragma unroll
    for (int mt = 0; mt < 4; mt++) {
        int lr0 = wm * 64 + mt * 16 + (lane >> 2);
        float s2a = 0.f, s2b = 0.f;
#pragma unroll
        for (int nt = 0; nt < NT; nt++) {
            int col = wn * NT * 8 + nt * 8 + (lane & 3) * 2;
            float d0 = acc[mt][nt][0] + biasS[col];
            float d1 = acc[mt][nt][1] + biasS[col + 1];
            float d2 = acc[mt][nt][2] + biasS[col];
            float d3 = acc[mt][nt][3] + biasS[col + 1];
            if (ACT) {
                d0 = fmaxf(d0, 0.f); d1 = fmaxf(d1, 0.f);
                d2 = fmaxf(d2, 0.f); d3 = fmaxf(d3, 0.f);
            }
            if (MODE == 3) {
                d0 = d0 > 0.f ? d0 : expm1f(d0);
                d1 = d1 > 0.f ? d1 : expm1f(d1);
                d2 = d2 > 0.f ? d2 : expm1f(d2);
                d3 = d3 > 0.f ? d3 : expm1f(d3);
                s2a = fmaf(d0, a2S[col], fmaf(d1, a2S[col + 1], s2a));
                s2b = fmaf(d2, a2S[col], fmaf(d3, a2S[col + 1], s2b));
            }
            int row0 = rbase + lr0;
            int row1 = row0 + 8;
            if (row0 < nrows) {
                *(float2*)(Cg + (size_t)row0 * BN + col) = make_float2(d0, d1);
                if (H16) *(__half2*)(hf16o + (size_t)row0 * BN + col) = __floats2half2_rn(d0, d1);
            }
            if (row1 < nrows) {
                *(float2*)(Cg + (size_t)row1 * BN + col) = make_float2(d2, d3);
                if (H16) *(__half2*)(hf16o + (size_t)row1 * BN + col) = __floats2half2_rn(d2, d3);
            }
        }
        if (MODE == 3) {
#pragma unroll
            for (int off = 1; off <= 2; off <<= 1) {
                s2a += __shfl_xor_sync(0xffffffffu, s2a, off);
                s2b += __shfl_xor_sync(0xffffffffu, s2b, off);
            }
            if ((lane & 3) == 0) {
                s2p[wn][lr0]     = s2a;
                s2p[wn][lr0 + 8] = s2b;
            }
        }
    }

    if (MODE == 3) {
        __syncthreads();
        if (tid < 128) {
            int row = rbase + tid;
            if (row < nrows) {
                float c2v = __ldg(c2p);
                h1o[row] = s2p[0][tid] + s2p[1][tid] + s2p[2][tid] + s2p[3][tid] + c2v;
            }
        }
    }
}

// ---------------- CSR aggregation (one warp per TWO destination nodes) --------
// u[n] = (sum_e w1_e * h[t_e] + w2[n]*x[n]) / (sum_e w1_e + w2[n])   (no elu)
// Interleaved A/B node processing doubles in-flight gather loads (MLP 16).
__global__ void agg_kernel(const __half2* __restrict__ hsrc16, const float* __restrict__ xg,
                           const float* __restrict__ x1a, const float* __restrict__ w2a,
                           const float* __restrict__ h1g,
                           float* __restrict__ uout) {
    int g = (blockIdx.x * blockDim.x + threadIdx.x) >> 5;
    int lane = threadIdx.x & 31;
    int nA = 2 * g, nB = 2 * g + 1;
    if (nA >= NN) return;
    const bool hasB = (nB < NN);

    float x1A = x1a[nA], w2A = w2a[nA];
    float x1B = hasB ? x1a[nB] : 0.f, w2B = hasB ? w2a[nB] : 0.f;
    float4 accA = *(const float4*)(xg + (size_t)nA * NH + lane * 4);
    accA.x *= w2A; accA.y *= w2A; accA.z *= w2A; accA.w *= w2A;
    float4 accB = make_float4(0.f, 0.f, 0.f, 0.f);
    if (hasB) {
        accB = *(const float4*)(xg + (size_t)nB * NH + lane * 4);
        accB.x *= w2B; accB.y *= w2B; accB.z *= w2B; accB.w *= w2B;
    }
    float divA = 0.f, divB = 0.f;

    const int a0 = g_rowptr[nA], a1 = g_rowptr[nA + 1];
    const int b0 = hasB ? a1 : 0;
    const int b1 = hasB ? g_rowptr[nB + 1] : 0;

    int abase = a0, bbase = b0;
    while (abase < a1 || bbase < b1) {
        // weight phase for both nodes (independent -> overlapped latency)
        float wA = 0.f, wB = 0.f;
        int tA = 0, tB = 0;
        int eA = abase + lane;
        int eB = bbase + lane;
        if (eA < a1) tA = g_et[eA];
        if (eB < b1) tB = g_et[eB];
        if (eA < a1) {
            float z = x1A + __ldg(&h1g[tA]);
            z = z > 0.f ? z : 0.2f * z;
            wA = __expf(z);
        }
        if (eB < b1) {
            float z = x1B + __ldg(&h1g[tB]);
            z = z > 0.f ? z : 0.2f * z;
            wB = __expf(z);
        }
        divA += wA; divB += wB;
        int cntA = a1 - abase; if (cntA > 32) cntA = 32; if (cntA < 0) cntA = 0;
        int cntB = b1 - bbase; if (cntB > 32) cntB = 32; if (cntB < 0) cntB = 0;
        int cnt = cntA > cntB ? cntA : cntB;
#pragma unroll 4
        for (int j = 0; j < cnt; j++) {
            float wAj = __shfl_sync(0xffffffffu, wA, j);
            int   tAj = __shfl_sync(0xffffffffu, tA, j);
            float wBj = __shfl_sync(0xffffffffu, wB, j);
            int   tBj = __shfl_sync(0xffffffffu, tB, j);
            if (j < cntA) {
                uint2 raw = *(const uint2*)(hsrc16 + (size_t)tAj * 64 + lane * 2);
                float2 f0 = __half22float2(*(__half2*)&raw.x);
                float2 f1 = __half22float2(*(__half2*)&raw.y);
                accA.x = fmaf(wAj, f0.x, accA.x);
                accA.y = fmaf(wAj, f0.y, accA.y);
                accA.z = fmaf(wAj, f1.x, accA.z);
                accA.w = fmaf(wAj, f1.y, accA.w);
            }
            if (j < cntB) {
                uint2 raw = *(const uint2*)(hsrc16 + (size_t)tBj * 64 + lane * 2);
                float2 f0 = __half22float2(*(__half2*)&raw.x);
                float2 f1 = __half22float2(*(__half2*)&raw.y);
                accB.x = fmaf(wBj, f0.x, accB.x);
                accB.y = fmaf(wBj, f0.y, accB.y);
                accB.z = fmaf(wBj, f1.x, accB.z);
                accB.w = fmaf(wBj, f1.y, accB.w);
            }
        }
        abase += 32; bbase += 32;
    }
#pragma unroll
    for (int off = 16; off; off >>= 1) {
        divA += __shfl_xor_sync(0xffffffffu, divA, off);
        divB += __shfl_xor_sync(0xffffffffu, divB, off);
    }
    float invA = 1.0f / (w2A + divA);
    float4 oA;
    oA.x = accA.x * invA; oA.y = accA.y * invA; oA.z = accA.z * invA; oA.w = accA.w * invA;
    *(float4*)(uout + (size_t)nA * NH + lane * 4) = oA;
    if (hasB) {
        float invB = 1.0f / (w2B + divB);
        float4 oB;
        oB.x = accB.x * invB; oB.y = accB.y * invB; oB.z = accB.z * invB; oB.w = accB.w * invB;
        *(float4*)(uout + (size_t)nB * NH + lane * 4) = oB;
    }
}

// ---------------- launch -----------------------------------------------------
extern "C" void kernel_launch(void* const* d_in, const int* in_sizes, int n_in,
                              void* d_out, int out_size) {
    const float* x    = (const float*)d_in[0];
    const int*   s    = (const int*)  d_in[1];
    const int*   t    = (const int*)  d_in[2];
    const float* fc1W = (const float*)d_in[3];
    const float* fc1b = (const float*)d_in[4];
    const float* fcsW = (const float*)d_in[5];
    const float* fcsb = (const float*)d_in[6];
    const float* a1   = (const float*)d_in[7];
    const float* a2   = (const float*)d_in[8];
    const float* fc2W = (const float*)d_in[9];
    const float* fc2b = (const float*)d_in[10];
    float* out = (float*)d_out;

    float *px, *ph, *pu, *px1all, *pw2all, *ph1, *ph1x, *pav2, *pcc;
    __half *pxf16, *phf16;
    int *pdeg;
    __nv_bfloat16 *w1h, *w1l, *wsh, *wsl, *w2h, *w2l;
    cudaGetSymbolAddress((void**)&px,  g_x);
    cudaGetSymbolAddress((void**)&ph,  g_h);
    cudaGetSymbolAddress((void**)&pu,  g_u);
    cudaGetSymbolAddress((void**)&pxf16, g_xf16);
    cudaGetSymbolAddress((void**)&phf16, g_hf16);
    cudaGetSymbolAddress((void**)&px1all, g_x1all);
    cudaGetSymbolAddress((void**)&pw2all, g_w2all);
    cudaGetSymbolAddress((void**)&ph1, g_h1);
    cudaGetSymbolAddress((void**)&ph1x, g_h1x);
    cudaGetSymbolAddress((void**)&pav2, g_av2);
    cudaGetSymbolAddress((void**)&pcc, g_cc);
    cudaGetSymbolAddress((void**)&pdeg, g_deg);
    cudaGetSymbolAddress((void**)&w1h, g_w1h);
    cudaGetSymbolAddress((void**)&w1l, g_w1l);
    cudaGetSymbolAddress((void**)&wsh, g_wsh);
    cudaGetSymbolAddress((void**)&wsl, g_wsl);
    cudaGetSymbolAddress((void**)&w2h, g_w2h);
    cudaGetSymbolAddress((void**)&w2l, g_w2l);

    // side stream + events (host-side objects only; created once)
    static cudaStream_t sstr = 0;
    static cudaEvent_t evStart, evCSR;
    if (!sstr) {
        cudaStreamCreateWithFlags(&sstr, cudaStreamNonBlocking);
        cudaEventCreateWithFlags(&evStart, cudaEventDisableTiming);
        cudaEventCreateWithFlags(&evCSR,   cudaEventDisableTiming);
        cudaFuncSetAttribute(scan_kernel, cudaFuncAttributeMaxDynamicSharedMemorySize, SCAN_SMEM);
    }

    const int gx = NTILE;   // 391 row-tiles
    const int aggBlocks = ((NN + 1) / 2 + 7) / 8;   // 25000 warps, 8 per block

    // fork CSR immediately (depends only on s, t)
    cudaEventRecord(evStart, 0);
    cudaStreamWaitEvent(sstr, evStart, 0);
    cudaMemsetAsync(pdeg, 0, NN * sizeof(int), sstr);
    hist_kernel<<<(EE + 255) / 256, 256, 0, sstr>>>(s);
    scan_kernel<<<1, 1024, SCAN_SMEM, sstr>>>();
    scatter_kernel<<<(EE + 255) / 256, 256, 0, sstr>>>(s, t);
    cudaEventRecord(evCSR, sstr);

    // main: weight pre-split + attention-vector precompute
    convW_kernel<<<(32768 + NHOP * 16384 + 8192 + 255) / 256, 256>>>(fc1W, fcsW, fc2W);
    prepvec_kernel<<<NHOP, 128>>>(fcsW, fcsb, a1, a2);

    // main: fc1 = relu(x_in @ fc1W^T + fc1b)  -> x (= h_0) + fp16 plane
    mma_gemm<256, 128, 1, 0, 1><<<gx, 256>>>(
        x, w1h, w1l, fc1b, px, pxf16, (const float*)0, (float*)0, (const float*)0, NN);

    // main: per-node scalars for all hops (x1_i, w2_i, h1_0)
    xdots_kernel<<<(NN + 7) / 8, 256>>>(px);

    // main: serial chain  agg_i -> GEMM_i  (h_{i+1} = elu(u_i @ W_i^T + b_i))
    cudaStreamWaitEvent(0, evCSR, 0);
    for (int i = 0; i < NHOP; i++) {
        const __half2* hsrc16 = (const __half2*)((i == 0) ? pxf16 : phf16);
        agg_kernel<<<aggBlocks, 256>>>(hsrc16, px, px1all + (size_t)i * NN,
                                       pw2all + (size_t)i * NN, ph1, pu);
        const float* a2n = (i + 1 < NHOP) ? (pav2 + (size_t)(i + 1) * 128)
                                          : (pav2 + (size_t)(NHOP - 1) * 128);
        const float* c2n = (i + 1 < NHOP) ? (pcc + 2 * (i + 1) + 1) : (pcc + 2 * (NHOP - 1) + 1);
        float* h1dst = (i + 1 < NHOP) ? ph1 : ph1x;
        mma_gemm<128, 128, 0, 3, 1><<<gx, 256>>>(
            pu, wsh + (size_t)i * 16384, wsl + (size_t)i * 16384, fcsb + (size_t)i * 128,
            ph, phf16, a2n, h1dst, c2n, NN);
    }

    // out = h_10 @ fc2W^T + fc2b
    mma_gemm<128, 64, 0, 0, 0><<<gx, 256>>>(
        ph, w2h, w2l, fc2b, out, (__half*)0,
        (const float*)0, (float*)0, (const float*)0, NN);
    (void)in_sizes; (void)n_in; (void)out_size;
}

// round 17
// speedup vs baseline: 1.1060x; 1.1060x over previous
#include <cuda_runtime.h>
#include <cuda_bf16.h>
#include <cuda_fp16.h>
#include <math.h>

#define NN 50000
#define EE 800000
#define NIN 256
#define NH 128
#define NOUT 64
#define NHOP 10
#define NTILE 391          // ceil(NN/128)

typedef unsigned int u32;

// ---------------- scratch (static device memory; no allocations) -------------
__device__ float g_x [(size_t)NN * NH];   // fc1 output = h_0
__device__ float g_h [(size_t)NN * NH];   // fp32 h (only hop 9 writes; fc2 reads)
__device__ float g_u [(size_t)NN * NH];   // agg output (pre-GEMM)
__device__ __align__(16) __half g_xf16[(size_t)NN * NH];  // fp16 x (gather + self plane)
__device__ __align__(16) __half g_hf16[(size_t)NN * NH];  // fp16 h (gather plane)
__device__ float g_x1all[NHOP * NN];
__device__ float g_w2all[NHOP * NN];
__device__ float g_h1[NN];
__device__ float g_h1x[NN];               // sink for last hop's unused h1
__device__ float g_av1[NHOP * NH];        // a1_i @ W_i
__device__ float g_av2[NHOP * NH];        // a2_i @ W_i
__device__ float g_cc[NHOP * 2];          // c1_i = a1_i.b_i, c2_i = a2_i.b_i
__device__ int   g_deg[NN];
__device__ int   g_rowptr[NN + 1];
__device__ int   g_cursor[NN];
__device__ int   g_et[EE];
// pre-split weights (bf16 hi/lo planes)
__device__ __nv_bfloat16 g_w1h[128 * 256], g_w1l[128 * 256];
__device__ __nv_bfloat16 g_wsh[NHOP * 128 * 128], g_wsl[NHOP * 128 * 128];
__device__ __nv_bfloat16 g_w2h[64 * 128],  g_w2l[64 * 128];

// ---------------- mma / ldmatrix helpers --------------------------------------
__device__ __forceinline__ void mma_bf16(float* d, const u32* a, const u32* b) {
    asm volatile(
        "mma.sync.aligned.m16n8k16.row.col.f32.bf16.bf16.f32 "
        "{%0,%1,%2,%3}, {%4,%5,%6,%7}, {%8,%9}, {%0,%1,%2,%3};"
        : "+f"(d[0]), "+f"(d[1]), "+f"(d[2]), "+f"(d[3])
        : "r"(a[0]), "r"(a[1]), "r"(a[2]), "r"(a[3]), "r"(b[0]), "r"(b[1]));
}

__device__ __forceinline__ void ldsm_x4(u32& r0, u32& r1, u32& r2, u32& r3, u32 addr) {
    asm volatile("ldmatrix.sync.aligned.m8n8.x4.shared.b16 {%0,%1,%2,%3}, [%4];"
        : "=r"(r0), "=r"(r1), "=r"(r2), "=r"(r3) : "r"(addr));
}

// ---------------- weight pre-split kernel ------------------------------------
__global__ void convW_kernel(const float* __restrict__ fc1W,
                             const float* __restrict__ fcsW,
                             const float* __restrict__ fc2W) {
    int i = blockIdx.x * blockDim.x + threadIdx.x;
    float v;
    __nv_bfloat16 *H, *L;
    if (i < 32768) {
        v = fc1W[i]; H = g_w1h + i; L = g_w1l + i;
    } else if (i < 32768 + NHOP * 16384) {
        int j = i - 32768;
        v = fcsW[j]; H = g_wsh + j; L = g_wsl + j;
    } else if (i < 32768 + NHOP * 16384 + 8192) {
        int j = i - 32768 - NHOP * 16384;
        v = fc2W[j]; H = g_w2h + j; L = g_w2l + j;
    } else return;
    __nv_bfloat16 h = __float2bfloat16(v);
    *H = h;
    *L = __float2bfloat16(v - __bfloat162float(h));
}

// ---------------- attention-vector precompute --------------------------------
__global__ void prepvec_kernel(const float* __restrict__ fcsW, const float* __restrict__ fcsb,
                               const float* __restrict__ a1, const float* __restrict__ a2) {
    int hop = blockIdx.x;
    int tid = threadIdx.x;
    __shared__ float a1s[128], a2s[128];
    a1s[tid] = a1[hop * 128 + tid];
    a2s[tid] = a2[hop * 128 + tid];
    __syncthreads();
    const float* W = fcsW + (size_t)hop * 16384;
    float s1 = 0.f, s2 = 0.f;
    for (int j = 0; j < 128; j++) {
        float w = W[j * 128 + tid];
        s1 = fmaf(a1s[j], w, s1);
        s2 = fmaf(a2s[j], w, s2);
    }
    g_av1[hop * 128 + tid] = s1;
    g_av2[hop * 128 + tid] = s2;
    if (tid == 0) {
        float c1 = 0.f, c2 = 0.f;
        const float* b = fcsb + hop * 128;
        for (int j = 0; j < 128; j++) { c1 = fmaf(a1s[j], b[j], c1); c2 = fmaf(a2s[j], b[j], c2); }
        g_cc[hop * 2] = c1;
        g_cc[hop * 2 + 1] = c2;
    }
}

// ---------------- per-node scalars for all hops (reads x once) ----------------
__global__ void xdots_kernel(const float* __restrict__ xg) {
    int n = (blockIdx.x * blockDim.x + threadIdx.x) >> 5;
    int lane = threadIdx.x & 31;
    if (n >= NN) return;
    float4 xv = *(const float4*)(xg + (size_t)n * NH + lane * 4);
#pragma unroll
    for (int i = 0; i < NHOP; i++) {
        float4 v1 = __ldg((const float4*)(g_av1 + i * 128 + lane * 4));
        float4 v2 = __ldg((const float4*)(g_av2 + i * 128 + lane * 4));
        float p1 = xv.x * v1.x + xv.y * v1.y + xv.z * v1.z + xv.w * v1.w;
        float p2 = xv.x * v2.x + xv.y * v2.y + xv.z * v2.z + xv.w * v2.w;
#pragma unroll
        for (int off = 16; off; off >>= 1) {
            p1 += __shfl_xor_sync(0xffffffffu, p1, off);
            p2 += __shfl_xor_sync(0xffffffffu, p2, off);
        }
        if (lane == 0) {
            float c1 = g_cc[i * 2], c2 = g_cc[i * 2 + 1];
            float x1 = p1 + c1;
            g_x1all[i * NN + n] = x1;
            float z = x1 + p2 + c2;
            z = z > 0.f ? z : 0.2f * z;
            g_w2all[i * NN + n] = __expf(z);
            if (i == 0) g_h1[n] = p2 + c2;
        }
    }
}

// ---------------- CSR build --------------------------------------------------
__global__ void hist_kernel(const int* __restrict__ s) {
    int e = blockIdx.x * blockDim.x + threadIdx.x;
    if (e < EE) atomicAdd(&g_deg[s[e]], 1);
}

#define SCAN_SMEM (NN * 4)
__global__ void scan_kernel() {
    extern __shared__ int sdeg[];
    __shared__ int wsum[32];
    __shared__ int totalS;
    const int tid = threadIdx.x, lane = tid & 31, wid = tid >> 5;
    for (int i = tid; i < NN; i += 1024) sdeg[i] = g_deg[i];
    __syncthreads();
    const int CH = (NN + 1023) / 1024;   // 49
    const int base = tid * CH;
    int s = 0;
#pragma unroll 7
    for (int i = 0; i < CH; i++) {
        int idx = base + i;
        if (idx < NN) s += sdeg[idx];
    }
    int v = s;
#pragma unroll
    for (int off = 1; off < 32; off <<= 1) {
        int n = __shfl_up_sync(0xffffffffu, v, off);
        if (lane >= off) v += n;
    }
    if (lane == 31) wsum[wid] = v;
    __syncthreads();
    if (wid == 0) {
        int w = wsum[lane];
#pragma unroll
        for (int off = 1; off < 32; off <<= 1) {
            int n = __shfl_up_sync(0xffffffffu, w, off);
            if (lane >= off) w += n;
        }
        wsum[lane] = w;
        if (lane == 31) totalS = w;
    }
    __syncthreads();
    int excl = v - s + (wid ? wsum[wid - 1] : 0);
    int run = excl;
#pragma unroll 7
    for (int i = 0; i < CH; i++) {
        int idx = base + i;
        if (idx < NN) {
            int d = sdeg[idx];
            sdeg[idx] = run;
            run += d;
        }
    }
    __syncthreads();
    for (int i = tid; i < NN; i += 1024) {
        int p = sdeg[i];
        g_cursor[i] = p;
        g_rowptr[i] = p;
    }
    if (tid == 0) g_rowptr[NN] = totalS;
}

__global__ void scatter_kernel(const int* __restrict__ s, const int* __restrict__ t) {
    int e = blockIdx.x * blockDim.x + threadIdx.x;
    if (e < EE) {
        int pos = atomicAdd(&g_cursor[s[e]], 1);
        g_et[pos] = t[e];
    }
}

// ---------------- bf16 3-product mma GEMM (ldmatrix fragment loads) -----------
// C[nrows,BN] = epi(A[nrows,KTOT] @ W[BN,KTOT]^T + bias), W pre-split hi/lo.
// MODE 0: epi = (ACT? relu : id). MODE 3: epi = elu, plus h1o[row] = C.a2g + *c2p.
// H16: write fp16 copy of C. F32C: write fp32 C (skipped for dead h planes).
template <int KTOT, int BN, int ACT, int MODE, int H16, int F32C>
__global__ __launch_bounds__(256)
void mma_gemm(const float* __restrict__ Ag,
              const __nv_bfloat16* __restrict__ Whg, const __nv_bfloat16* __restrict__ Wlg,
              const float* __restrict__ biasg,
              float* __restrict__ Cg, __half* __restrict__ hf16o,
              const float* __restrict__ a2g, float* __restrict__ h1o,
              const float* __restrict__ c2p,
              int nrows) {
    constexpr int NT  = BN / 32;
    constexpr int NCH = KTOT / 32;
    constexpr int WIT = BN / 64;
    constexpr int SP  = 20;

    __shared__ float biasS[BN];
    __shared__ float a2S[128];
    __shared__ float s2p[4][128];
    __shared__ __align__(16) u32 Ah[128 * SP], Al[128 * SP];
    __shared__ __align__(16) u32 Wsh[BN * SP], Wsl[BN * SP];

    const int tid = threadIdx.x;
    const int wid = tid >> 5, lane = tid & 31;
    const int wm = wid >> 2, wn = wid & 3;
    const int rbase = blockIdx.x * 128;

    if (tid < BN) biasS[tid] = biasg[tid];
    if (MODE == 3 && tid < 128) a2S[tid] = a2g[tid];

    const u32 AhS = (u32)__cvta_generic_to_shared(Ah);
    const u32 AlS = (u32)__cvta_generic_to_shared(Al);
    const u32 WhS = (u32)__cvta_generic_to_shared(Wsh);
    const u32 WlS = (u32)__cvta_generic_to_shared(Wsl);
    const u32 aoff = (u32)(((wm * 64 + (lane & 15)) * SP + (lane >> 4) * 4) * 4);
    const u32 boff = (u32)(((wn * (NT * 8) + (lane & 7) + ((lane >> 4) << 3)) * SP
                           + ((lane >> 3) & 1) * 4) * 4);

    float acc[4][NT][4];
#pragma unroll
    for (int mt = 0; mt < 4; mt++)
#pragma unroll
        for (int nt = 0; nt < NT; nt++)
#pragma unroll
            for (int q = 0; q < 4; q++) acc[mt][nt][q] = 0.f;

    float4 pa[4];
    uint4 pwh[WIT], pwl[WIT];
#pragma unroll
    for (int it = 0; it < 4; it++) {
        int idx = tid + it * 256;
        int r = idx >> 3, kq = idx & 7;
        int row = rbase + r;
        pa[it] = (row < nrows) ? *(const float4*)(Ag + (size_t)row * KTOT + kq * 4)
                               : make_float4(0.f, 0.f, 0.f, 0.f);
    }
#pragma unroll
    for (int it = 0; it < WIT; it++) {
        int idx = tid + it * 256;
        int r = idx >> 2, q = idx & 3;
        pwh[it] = ((const uint4*)(Whg + (size_t)r * KTOT))[q];
        pwl[it] = ((const uint4*)(Wlg + (size_t)r * KTOT))[q];
    }

    for (int c = 0; c < NCH; c++) {
#pragma unroll
        for (int it = 0; it < 4; it++) {
            int idx = tid + it * 256;
            int r = idx >> 3, kq = idx & 7;
            float4 v = pa[it];
            __nv_bfloat162 hxy = __floats2bfloat162_rn(v.x, v.y);
            __nv_bfloat162 hzw = __floats2bfloat162_rn(v.z, v.w);
            float2 fxy = __bfloat1622float2(hxy);
            float2 fzw = __bfloat1622float2(hzw);
            __nv_bfloat162 lxy = __floats2bfloat162_rn(v.x - fxy.x, v.y - fxy.y);
            __nv_bfloat162 lzw = __floats2bfloat162_rn(v.z - fzw.x, v.w - fzw.y);
            int o = r * SP + kq * 2;
            Ah[o]     = *(u32*)&hxy;  Ah[o + 1] = *(u32*)&hzw;
            Al[o]     = *(u32*)&lxy;  Al[o + 1] = *(u32*)&lzw;
        }
#pragma unroll
        for (int it = 0; it < WIT; it++) {
            int idx = tid + it * 256;
            int r = idx >> 2, q = idx & 3;
            *(uint4*)&Wsh[r * SP + q * 4] = pwh[it];
            *(uint4*)&Wsl[r * SP + q * 4] = pwl[it];
        }
        __syncthreads();

        if (c + 1 < NCH) {
            const int kc = (c + 1) * 32;
#pragma unroll
            for (int it = 0; it < 4; it++) {
                int idx = tid + it * 256;
                int r = idx >> 3, kq = idx & 7;
                int row = rbase + r;
                pa[it] = (row < nrows) ? *(const float4*)(Ag + (size_t)row * KTOT + kc + kq * 4)
                                       : make_float4(0.f, 0.f, 0.f, 0.f);
            }
#pragma unroll
            for (int it = 0; it < WIT; it++) {
                int idx = tid + it * 256;
                int r = idx >> 2, q = idx & 3;
                pwh[it] = ((const uint4*)(Whg + (size_t)r * KTOT + kc))[q];
                pwl[it] = ((const uint4*)(Wlg + (size_t)r * KTOT + kc))[q];
            }
        }

#pragma unroll
        for (int s = 0; s < 2; s++) {
            u32 ah[4][4], al[4][4], bh[NT][2], bl[NT][2];
            const u32 soff = (u32)(s * 8 * 4);
#pragma unroll
            for (int mt = 0; mt < 4; mt++) {
                u32 moff = aoff + (u32)(mt * 16 * SP * 4) + soff;
                ldsm_x4(ah[mt][0], ah[mt][1], ah[mt][2], ah[mt][3], AhS + moff);
                ldsm_x4(al[mt][0], al[mt][1], al[mt][2], al[mt][3], AlS + moff);
            }
#pragma unroll
            for (int np = 0; np < NT / 2; np++) {
                u32 noff = boff + (u32)(np * 16 * SP * 4) + soff;
                ldsm_x4(bh[2 * np][0], bh[2 * np][1], bh[2 * np + 1][0], bh[2 * np + 1][1],
                        WhS + noff);
                ldsm_x4(bl[2 * np][0], bl[2 * np][1], bl[2 * np + 1][0], bl[2 * np + 1][1],
                        WlS + noff);
            }
#pragma unroll
            for (int mt = 0; mt < 4; mt++)
#pragma unroll
                for (int nt = 0; nt < NT; nt++) {
                    mma_bf16(acc[mt][nt], ah[mt], bh[nt]);
                    mma_bf16(acc[mt][nt], ah[mt], bl[nt]);
                    mma_bf16(acc[mt][nt], al[mt], bh[nt]);
                }
        }
        if (c + 1 < NCH) __syncthreads();
    }

#pragma unroll
    for (int mt = 0; mt < 4; mt++) {
        int lr0 = wm * 64 + mt * 16 + (lane >> 2);
        float s2a = 0.f, s2b = 0.f;
#pragma unroll
        for (int nt = 0; nt < NT; nt++) {
            int col = wn * NT * 8 + nt * 8 + (lane & 3) * 2;
            float d0 = acc[mt][nt][0] + biasS[col];
            float d1 = acc[mt][nt][1] + biasS[col + 1];
            float d2 = acc[mt][nt][2] + biasS[col];
            float d3 = acc[mt][nt][3] + biasS[col + 1];
            if (ACT) {
                d0 = fmaxf(d0, 0.f); d1 = fmaxf(d1, 0.f);
                d2 = fmaxf(d2, 0.f); d3 = fmaxf(d3, 0.f);
            }
            if (MODE == 3) {
                d0 = d0 > 0.f ? d0 : expm1f(d0);
                d1 = d1 > 0.f ? d1 : expm1f(d1);
                d2 = d2 > 0.f ? d2 : expm1f(d2);
                d3 = d3 > 0.f ? d3 : expm1f(d3);
                s2a = fmaf(d0, a2S[col], fmaf(d1, a2S[col + 1], s2a));
                s2b = fmaf(d2, a2S[col], fmaf(d3, a2S[col + 1], s2b));
            }
            int row0 = rbase + lr0;
            int row1 = row0 + 8;
            if (row0 < nrows) {
                if (F32C) *(float2*)(Cg + (size_t)row0 * BN + col) = make_float2(d0, d1);
                if (H16)  *(__half2*)(hf16o + (size_t)row0 * BN + col) = __floats2half2_rn(d0, d1);
            }
            if (row1 < nrows) {
                if (F32C) *(float2*)(Cg + (size_t)row1 * BN + col) = make_float2(d2, d3);
                if (H16)  *(__half2*)(hf16o + (size_t)row1 * BN + col) = __floats2half2_rn(d2, d3);
            }
        }
        if (MODE == 3) {
#pragma unroll
            for (int off = 1; off <= 2; off <<= 1) {
                s2a += __shfl_xor_sync(0xffffffffu, s2a, off);
                s2b += __shfl_xor_sync(0xffffffffu, s2b, off);
            }
            if ((lane & 3) == 0) {
                s2p[wn][lr0]     = s2a;
                s2p[wn][lr0 + 8] = s2b;
            }
        }
    }

    if (MODE == 3) {
        __syncthreads();
        if (tid < 128) {
            int row = rbase + tid;
            if (row < nrows) {
                float c2v = __ldg(c2p);
                h1o[row] = s2p[0][tid] + s2p[1][tid] + s2p[2][tid] + s2p[3][tid] + c2v;
            }
        }
    }
}

// ---------------- CSR aggregation (one warp per destination node) ------------
// u[n] = (sum_e w1_e * h[t_e] + w2[n]*x[n]) / (sum_e w1_e + w2[n])   (no elu)
// Neighbor rows AND self term gathered from fp16 planes (minimal traffic).
__global__ void agg_kernel(const __half2* __restrict__ hsrc16, const __half2* __restrict__ xg16,
                           const float* __restrict__ x1a, const float* __restrict__ w2a,
                           const float* __restrict__ h1g,
                           float* __restrict__ uout) {
    int n = (blockIdx.x * blockDim.x + threadIdx.x) >> 5;
    int lane = threadIdx.x & 31;
    if (n >= NN) return;

    float x1n = x1a[n];
    float w2n = w2a[n];
    uint2 sraw = *(const uint2*)(xg16 + (size_t)n * 64 + lane * 2);
    float2 s0 = __half22float2(*(__half2*)&sraw.x);
    float2 s1 = __half22float2(*(__half2*)&sraw.y);
    float4 acc = make_float4(s0.x * w2n, s0.y * w2n, s1.x * w2n, s1.y * w2n);
    float divacc = 0.f;

    const int e0 = g_rowptr[n];
    const int e1 = g_rowptr[n + 1];
    for (int eb = e0; eb < e1; eb += 32) {
        int e = eb + lane;
        float w = 0.f;
        int tj = 0;
        if (e < e1) {
            tj = g_et[e];
            float z = x1n + __ldg(&h1g[tj]);
            z = z > 0.f ? z : 0.2f * z;
            w = __expf(z);
        }
        divacc += w;
        int cnt = min(32, e1 - eb);
#pragma unroll 8
        for (int j = 0; j < cnt; j++) {
            float wj = __shfl_sync(0xffffffffu, w, j);
            int tjj  = __shfl_sync(0xffffffffu, tj, j);
            uint2 raw = *(const uint2*)(hsrc16 + (size_t)tjj * 64 + lane * 2);
            float2 f0 = __half22float2(*(__half2*)&raw.x);
            float2 f1 = __half22float2(*(__half2*)&raw.y);
            acc.x = fmaf(wj, f0.x, acc.x);
            acc.y = fmaf(wj, f0.y, acc.y);
            acc.z = fmaf(wj, f1.x, acc.z);
            acc.w = fmaf(wj, f1.y, acc.w);
        }
    }
#pragma unroll
    for (int off = 16; off; off >>= 1)
        divacc += __shfl_xor_sync(0xffffffffu, divacc, off);
    float inv = 1.0f / (w2n + divacc);
    float4 o;
    o.x = acc.x * inv; o.y = acc.y * inv; o.z = acc.z * inv; o.w = acc.w * inv;
    *(float4*)(uout + (size_t)n * NH + lane * 4) = o;
}

// ---------------- launch -----------------------------------------------------
extern "C" void kernel_launch(void* const* d_in, const int* in_sizes, int n_in,
                              void* d_out, int out_size) {
    const float* x    = (const float*)d_in[0];
    const int*   s    = (const int*)  d_in[1];
    const int*   t    = (const int*)  d_in[2];
    const float* fc1W = (const float*)d_in[3];
    const float* fc1b = (const float*)d_in[4];
    const float* fcsW = (const float*)d_in[5];
    const float* fcsb = (const float*)d_in[6];
    const float* a1   = (const float*)d_in[7];
    const float* a2   = (const float*)d_in[8];
    const float* fc2W = (const float*)d_in[9];
    const float* fc2b = (const float*)d_in[10];
    float* out = (float*)d_out;

    float *px, *ph, *pu, *px1all, *pw2all, *ph1, *ph1x, *pav2, *pcc;
    __half *pxf16, *phf16;
    int *pdeg;
    __nv_bfloat16 *w1h, *w1l, *wsh, *wsl, *w2h, *w2l;
    cudaGetSymbolAddress((void**)&px,  g_x);
    cudaGetSymbolAddress((void**)&ph,  g_h);
    cudaGetSymbolAddress((void**)&pu,  g_u);
    cudaGetSymbolAddress((void**)&pxf16, g_xf16);
    cudaGetSymbolAddress((void**)&phf16, g_hf16);
    cudaGetSymbolAddress((void**)&px1all, g_x1all);
    cudaGetSymbolAddress((void**)&pw2all, g_w2all);
    cudaGetSymbolAddress((void**)&ph1, g_h1);
    cudaGetSymbolAddress((void**)&ph1x, g_h1x);
    cudaGetSymbolAddress((void**)&pav2, g_av2);
    cudaGetSymbolAddress((void**)&pcc, g_cc);
    cudaGetSymbolAddress((void**)&pdeg, g_deg);
    cudaGetSymbolAddress((void**)&w1h, g_w1h);
    cudaGetSymbolAddress((void**)&w1l, g_w1l);
    cudaGetSymbolAddress((void**)&wsh, g_wsh);
    cudaGetSymbolAddress((void**)&wsl, g_wsl);
    cudaGetSymbolAddress((void**)&w2h, g_w2h);
    cudaGetSymbolAddress((void**)&w2l, g_w2l);

    // side stream + events (host-side objects only; created once)
    static cudaStream_t sstr = 0;
    static cudaEvent_t evStart, evCSR;
    if (!sstr) {
        cudaStreamCreateWithFlags(&sstr, cudaStreamNonBlocking);
        cudaEventCreateWithFlags(&evStart, cudaEventDisableTiming);
        cudaEventCreateWithFlags(&evCSR,   cudaEventDisableTiming);
        cudaFuncSetAttribute(scan_kernel, cudaFuncAttributeMaxDynamicSharedMemorySize, SCAN_SMEM);
    }

    const int gx = NTILE;   // 391 row-tiles

    // fork CSR immediately (depends only on s, t)
    cudaEventRecord(evStart, 0);
    cudaStreamWaitEvent(sstr, evStart, 0);
    cudaMemsetAsync(pdeg, 0, NN * sizeof(int), sstr);
    hist_kernel<<<(EE + 255) / 256, 256, 0, sstr>>>(s);
    scan_kernel<<<1, 1024, SCAN_SMEM, sstr>>>();
    scatter_kernel<<<(EE + 255) / 256, 256, 0, sstr>>>(s, t);
    cudaEventRecord(evCSR, sstr);

    // main: weight pre-split + attention-vector precompute
    convW_kernel<<<(32768 + NHOP * 16384 + 8192 + 255) / 256, 256>>>(fc1W, fcsW, fc2W);
    prepvec_kernel<<<NHOP, 128>>>(fcsW, fcsb, a1, a2);

    // main: fc1 = relu(x_in @ fc1W^T + fc1b)  -> x fp32 (xdots) + fp16 plane
    mma_gemm<256, 128, 1, 0, 1, 1><<<gx, 256>>>(
        x, w1h, w1l, fc1b, px, pxf16, (const float*)0, (float*)0, (const float*)0, NN);

    // main: per-node scalars for all hops (x1_i, w2_i, h1_0)
    xdots_kernel<<<(NN + 7) / 8, 256>>>(px);

    // main: serial chain  agg_i -> GEMM_i  (h_{i+1} = elu(u_i @ W_i^T + b_i))
    cudaStreamWaitEvent(0, evCSR, 0);
    for (int i = 0; i < NHOP; i++) {
        const __half2* hsrc16 = (const __half2*)((i == 0) ? pxf16 : phf16);
        agg_kernel<<<(NN + 7) / 8, 256>>>(hsrc16, (const __half2*)pxf16,
                                          px1all + (size_t)i * NN,
                                          pw2all + (size_t)i * NN, ph1, pu);
        const float* Wb = (const float*)(wsh + (size_t)i * 16384);   (void)Wb;
        if (i + 1 < NHOP) {
            // hops 0..8: fp32 h is dead -> write only fp16 plane + h1
            mma_gemm<128, 128, 0, 3, 1, 0><<<gx, 256>>>(
                pu, wsh + (size_t)i * 16384, wsl + (size_t)i * 16384, fcsb + (size_t)i * 128,
                ph, phf16, pav2 + (size_t)(i + 1) * 128, ph1, pcc + 2 * (i + 1) + 1, NN);
        } else {
            // hop 9: fp32 h needed by fc2; fp16 plane is dead
            mma_gemm<128, 128, 0, 3, 0, 1><<<gx, 256>>>(
                pu, wsh + (size_t)i * 16384, wsl + (size_t)i * 16384, fcsb + (size_t)i * 128,
                ph, phf16, pav2, ph1x, pcc + 1, NN);
        }
    }

    // out = h_10 @ fc2W^T + fc2b
    mma_gemm<128, 64, 0, 0, 0, 1><<<gx, 256>>>(
        ph, w2h, w2l, fc2b, out, (__half*)0,
        (const float*)0, (float*)0, (const float*)0, NN);
    (void)in_sizes; (void)n_in; (void)out_size;
}